// round 1
// baseline (speedup 1.0000x reference)
#include <cuda_runtime.h>

#define N_NODES  50000
#define N_EDGES  1600000
#define N_GRAPHS 1000

// ---------------- scratch (device globals; no allocation allowed) ----------
__device__ __align__(16) float g_aggr1[N_NODES * 8];    // layer1 aggregation (7 used, pad 8)
__device__ __align__(16) float g_h1[N_NODES * 64];      // layer1 output
__device__ __align__(16) float g_aggr2[N_NODES * 64];   // layer2 aggregation
__device__ __align__(16) float g_sums[N_GRAPHS * 64];   // pooled sums
__device__ __align__(16) float g_cnt[N_GRAPHS];         // per-graph node counts

// ---------------- zero scratch ---------------------------------------------
#define ZERO_TOTAL (N_NODES * 8 + N_NODES * 64 + N_GRAPHS * 64 + N_GRAPHS)
__global__ void zero_kernel() {
    int i = blockIdx.x * blockDim.x + threadIdx.x;
    if (i >= ZERO_TOTAL) return;
    if (i < N_NODES * 8) {
        g_aggr1[i] = 0.f;
    } else if (i < N_NODES * 8 + N_NODES * 64) {
        g_aggr2[i - N_NODES * 8] = 0.f;
    } else if (i < N_NODES * 8 + N_NODES * 64 + N_GRAPHS * 64) {
        g_sums[i - (N_NODES * 8 + N_NODES * 64)] = 0.f;
    } else {
        g_cnt[i - (N_NODES * 8 + N_NODES * 64 + N_GRAPHS * 64)] = 0.f;
    }
}

// ---------------- layer 1 edge pass (d = 7) --------------------------------
// msg = relu(x[src] + edge_attr @ We1 + be1); atomic scatter to aggr1[dst]
__global__ void edge1_kernel(const float* __restrict__ x,
                             const float* __restrict__ ea,
                             const int*   __restrict__ ei,
                             const float* __restrict__ We1,
                             const float* __restrict__ be1) {
    int e = blockIdx.x * blockDim.x + threadIdx.x;
    if (e >= N_EDGES) return;
    int src = ei[e];
    int dst = ei[N_EDGES + e];
    float4 a = reinterpret_cast<const float4*>(ea)[e];
#pragma unroll
    for (int j = 0; j < 7; j++) {
        float v = be1[j]
                + a.x * We1[0 * 7 + j]
                + a.y * We1[1 * 7 + j]
                + a.z * We1[2 * 7 + j]
                + a.w * We1[3 * 7 + j];
        v += x[src * 7 + j];
        v = fmaxf(v, 0.f);
        atomicAdd(&g_aggr1[dst * 8 + j], v);
    }
}

// ---------------- layer 1 node MLP: 7 -> 64 -> 64, warp per node -----------
__global__ void node1_kernel(const float* __restrict__ x,
                             const float* __restrict__ W1a,
                             const float* __restrict__ b1a,
                             const float* __restrict__ W1b,
                             const float* __restrict__ b1b) {
    __shared__ float sWa[7 * 64];
    __shared__ float sWb[64 * 64];
    __shared__ float sba[64];
    __shared__ float sbb[64];
    for (int i = threadIdx.x; i < 7 * 64; i += blockDim.x) sWa[i] = W1a[i];
    for (int i = threadIdx.x; i < 64 * 64; i += blockDim.x) sWb[i] = W1b[i];
    if (threadIdx.x < 64) { sba[threadIdx.x] = b1a[threadIdx.x]; sbb[threadIdx.x] = b1b[threadIdx.x]; }
    __syncthreads();

    int node = (blockIdx.x * blockDim.x + threadIdx.x) >> 5;
    int lane = threadIdx.x & 31;
    if (node >= N_NODES) return;

    float z[7];
#pragma unroll
    for (int k = 0; k < 7; k++)
        z[k] = x[node * 7 + k] + g_aggr1[node * 8 + k];

    int j = lane * 2;
    float t0 = sba[j], t1 = sba[j + 1];
#pragma unroll
    for (int k = 0; k < 7; k++) {
        t0 += z[k] * sWa[k * 64 + j];
        t1 += z[k] * sWa[k * 64 + j + 1];
    }
    t0 = fmaxf(t0, 0.f);
    t1 = fmaxf(t1, 0.f);

    float a0 = sbb[j], a1 = sbb[j + 1];
#pragma unroll
    for (int k = 0; k < 64; k++) {
        float tk = __shfl_sync(0xffffffffu, (k & 1) ? t1 : t0, k >> 1);
        a0 += tk * sWb[k * 64 + j];
        a1 += tk * sWb[k * 64 + j + 1];
    }
    g_h1[node * 64 + j]     = fmaxf(a0, 0.f);   // outer relu from reference
    g_h1[node * 64 + j + 1] = fmaxf(a1, 0.f);
}

// ---------------- layer 2 edge pass (d = 64), half-warp per edge -----------
// msg = relu(h1[src] + edge_attr @ We2 + be2); red.v4 scatter to aggr2[dst]
__global__ void edge2_kernel(const float* __restrict__ ea,
                             const int*   __restrict__ ei,
                             const float* __restrict__ We2,
                             const float* __restrict__ be2) {
    __shared__ float sW[4 * 64];
    __shared__ float sb[64];
    int tid = threadIdx.x;
    if (tid < 256) sW[tid] = We2[tid];
    if (tid < 64)  sb[tid] = be2[tid];
    __syncthreads();

    int gw   = (blockIdx.x * blockDim.x + tid) >> 5;  // global warp id
    int half = (tid >> 4) & 1;                        // which half-warp
    int l    = tid & 15;                              // lane within half-warp
    int e    = gw * 2 + half;
    if (e >= N_EDGES) return;

    int src = ei[e];
    int dst = ei[N_EDGES + e];
    float4 a = reinterpret_cast<const float4*>(ea)[e];
    int j = l * 4;

    float4 m;
    m.x = sb[j+0] + a.x*sW[j+0] + a.y*sW[64+j+0] + a.z*sW[128+j+0] + a.w*sW[192+j+0];
    m.y = sb[j+1] + a.x*sW[j+1] + a.y*sW[64+j+1] + a.z*sW[128+j+1] + a.w*sW[192+j+1];
    m.z = sb[j+2] + a.x*sW[j+2] + a.y*sW[64+j+2] + a.z*sW[128+j+2] + a.w*sW[192+j+2];
    m.w = sb[j+3] + a.x*sW[j+3] + a.y*sW[64+j+3] + a.z*sW[128+j+3] + a.w*sW[192+j+3];

    float4 h = reinterpret_cast<const float4*>(g_h1 + src * 64)[l];
    m.x = fmaxf(m.x + h.x, 0.f);
    m.y = fmaxf(m.y + h.y, 0.f);
    m.z = fmaxf(m.z + h.z, 0.f);
    m.w = fmaxf(m.w + h.w, 0.f);

    float* p = g_aggr2 + dst * 64 + j;
    asm volatile("red.global.add.v4.f32 [%0], {%1, %2, %3, %4};"
                 :: "l"(p), "f"(m.x), "f"(m.y), "f"(m.z), "f"(m.w)
                 : "memory");
}

// ---------------- layer 2 node MLP (64->64->64) + pool, warp per node ------
__global__ void node2pool_kernel(const int*   __restrict__ batch,
                                 const float* __restrict__ W2a,
                                 const float* __restrict__ b2a,
                                 const float* __restrict__ W2b,
                                 const float* __restrict__ b2b) {
    __shared__ float sWa[64 * 64];
    __shared__ float sWb[64 * 64];
    __shared__ float sba[64];
    __shared__ float sbb[64];
    for (int i = threadIdx.x; i < 64 * 64; i += blockDim.x) { sWa[i] = W2a[i]; sWb[i] = W2b[i]; }
    if (threadIdx.x < 64) { sba[threadIdx.x] = b2a[threadIdx.x]; sbb[threadIdx.x] = b2b[threadIdx.x]; }
    __syncthreads();

    int node = (blockIdx.x * blockDim.x + threadIdx.x) >> 5;
    int lane = threadIdx.x & 31;
    if (node >= N_NODES) return;

    int j = lane * 2;
    float2 hv = *reinterpret_cast<const float2*>(g_h1 + node * 64 + j);
    float2 av = *reinterpret_cast<const float2*>(g_aggr2 + node * 64 + j);
    float z0 = hv.x + av.x;
    float z1 = hv.y + av.y;

    float t0 = sba[j], t1 = sba[j + 1];
#pragma unroll
    for (int k = 0; k < 64; k++) {
        float zk = __shfl_sync(0xffffffffu, (k & 1) ? z1 : z0, k >> 1);
        t0 += zk * sWa[k * 64 + j];
        t1 += zk * sWa[k * 64 + j + 1];
    }
    t0 = fmaxf(t0, 0.f);
    t1 = fmaxf(t1, 0.f);

    float a0 = sbb[j], a1 = sbb[j + 1];
#pragma unroll
    for (int k = 0; k < 64; k++) {
        float tk = __shfl_sync(0xffffffffu, (k & 1) ? t1 : t0, k >> 1);
        a0 += tk * sWb[k * 64 + j];
        a1 += tk * sWb[k * 64 + j + 1];
    }
    a0 = fmaxf(a0, 0.f);   // outer relu from reference
    a1 = fmaxf(a1, 0.f);

    int g = batch[node];
    float* p = g_sums + g * 64 + j;
    asm volatile("red.global.add.v2.f32 [%0], {%1, %2};"
                 :: "l"(p), "f"(a0), "f"(a1) : "memory");
    if (lane == 0) atomicAdd(&g_cnt[g], 1.0f);
}

// ---------------- final FC: pooled[G,64] @ Wfc[64,12] + bfc -----------------
__global__ void fc_kernel(const float* __restrict__ Wfc,
                          const float* __restrict__ bfc,
                          float* __restrict__ out) {
    int i = blockIdx.x * blockDim.x + threadIdx.x;
    if (i >= N_GRAPHS * 12) return;
    int g = i / 12;
    int c = i % 12;
    float inv = 1.0f / fmaxf(g_cnt[g], 1.0f);
    float acc = 0.f;
#pragma unroll
    for (int k = 0; k < 64; k++)
        acc += g_sums[g * 64 + k] * Wfc[k * 12 + c];
    out[i] = bfc[c] + inv * acc;
}

// ---------------- launch ----------------------------------------------------
extern "C" void kernel_launch(void* const* d_in, const int* in_sizes, int n_in,
                              void* d_out, int out_size) {
    const float* x    = (const float*)d_in[0];
    const float* ea   = (const float*)d_in[1];
    const int*   ei   = (const int*)  d_in[2];
    const int*   batch= (const int*)  d_in[3];
    const float* We1  = (const float*)d_in[4];
    const float* be1  = (const float*)d_in[5];
    const float* W1a  = (const float*)d_in[6];
    const float* b1a  = (const float*)d_in[7];
    const float* W1b  = (const float*)d_in[8];
    const float* b1b  = (const float*)d_in[9];
    const float* We2  = (const float*)d_in[10];
    const float* be2  = (const float*)d_in[11];
    const float* W2a  = (const float*)d_in[12];
    const float* b2a  = (const float*)d_in[13];
    const float* W2b  = (const float*)d_in[14];
    const float* b2b  = (const float*)d_in[15];
    const float* Wfc  = (const float*)d_in[16];
    const float* bfc  = (const float*)d_in[17];
    float* out = (float*)d_out;

    zero_kernel<<<(ZERO_TOTAL + 255) / 256, 256>>>();
    edge1_kernel<<<(N_EDGES + 255) / 256, 256>>>(x, ea, ei, We1, be1);
    node1_kernel<<<(N_NODES * 32 + 255) / 256, 256>>>(x, W1a, b1a, W1b, b1b);
    edge2_kernel<<<(N_EDGES / 16), 256>>>(ea, ei, We2, be2);          // 16 edges / block
    node2pool_kernel<<<(N_NODES * 32 + 255) / 256, 256>>>(batch, W2a, b2a, W2b, b2b);
    fc_kernel<<<(N_GRAPHS * 12 + 255) / 256, 256>>>(Wfc, bfc, out);
}

// round 2
// speedup vs baseline: 1.1548x; 1.1548x over previous
#include <cuda_runtime.h>

#define N_NODES  50000
#define N_EDGES  1600000
#define N_GRAPHS 1000

// ---------------- scratch (device globals; no allocation allowed) ----------
__device__ __align__(16) float g_aggr1[N_NODES * 8];    // layer1 aggregation (7 used, pad 8)
__device__ __align__(16) float g_h1[N_NODES * 64];      // layer1 output
__device__ __align__(16) float g_aggr2[N_NODES * 64];   // layer2 aggregation
__device__ __align__(16) float g_sums[N_GRAPHS * 64];   // pooled sums
__device__ __align__(16) float g_cnt[N_GRAPHS];         // per-graph node counts

// ---------------- zero scratch (vectorized) ---------------------------------
#define ZERO_TOTAL4 ((N_NODES * 8 + N_NODES * 64 + N_GRAPHS * 64) / 4)
__global__ void zero_kernel() {
    int i = blockIdx.x * blockDim.x + threadIdx.x;
    const float4 z4 = make_float4(0.f, 0.f, 0.f, 0.f);
    if (i < N_NODES * 2) {
        reinterpret_cast<float4*>(g_aggr1)[i] = z4;
    } else if (i < N_NODES * 2 + N_NODES * 16) {
        reinterpret_cast<float4*>(g_aggr2)[i - N_NODES * 2] = z4;
    } else if (i < ZERO_TOTAL4) {
        reinterpret_cast<float4*>(g_sums)[i - (N_NODES * 2 + N_NODES * 16)] = z4;
    }
    if (i < N_GRAPHS) g_cnt[i] = 0.f;
}

// ---------------- layer 1 edge pass (d = 7), weights in registers ----------
// msg = relu(x[src] + edge_attr @ We1 + be1); 2x red.v4 scatter to aggr1[dst]
__global__ void edge1_kernel(const float* __restrict__ x,
                             const float* __restrict__ ea,
                             const int*   __restrict__ ei,
                             const float* __restrict__ We1,
                             const float* __restrict__ be1) {
    float w[4][7], b[7];
#pragma unroll
    for (int i = 0; i < 4; i++)
#pragma unroll
        for (int j = 0; j < 7; j++)
            w[i][j] = __ldg(&We1[i * 7 + j]);
#pragma unroll
    for (int j = 0; j < 7; j++) b[j] = __ldg(&be1[j]);

    int t  = blockIdx.x * blockDim.x + threadIdx.x;
    int nt = gridDim.x * blockDim.x;
    for (int e = t; e < N_EDGES; e += nt) {
        int src = __ldg(&ei[e]);
        int dst = __ldg(&ei[N_EDGES + e]);
        float4 a = __ldg(reinterpret_cast<const float4*>(ea) + e);
        float v[8];
#pragma unroll
        for (int j = 0; j < 7; j++) {
            float m = b[j] + a.x * w[0][j] + a.y * w[1][j]
                            + a.z * w[2][j] + a.w * w[3][j];
            m += __ldg(&x[src * 7 + j]);
            v[j] = fmaxf(m, 0.f);
        }
        v[7] = 0.f;
        float* p = g_aggr1 + dst * 8;
        asm volatile("red.global.add.v4.f32 [%0], {%1, %2, %3, %4};"
                     :: "l"(p), "f"(v[0]), "f"(v[1]), "f"(v[2]), "f"(v[3]) : "memory");
        asm volatile("red.global.add.v4.f32 [%0], {%1, %2, %3, %4};"
                     :: "l"(p + 4), "f"(v[4]), "f"(v[5]), "f"(v[6]), "f"(v[7]) : "memory");
    }
}

// ---------------- layer 1 node MLP: 7 -> 64 -> 64, warp per node, persistent
__global__ void node1_kernel(const float* __restrict__ x,
                             const float* __restrict__ W1a,
                             const float* __restrict__ b1a,
                             const float* __restrict__ W1b,
                             const float* __restrict__ b1b) {
    __shared__ float sWa[7 * 64];
    __shared__ float sWb[64 * 64];
    __shared__ float sba[64];
    __shared__ float sbb[64];
    for (int i = threadIdx.x; i < 7 * 64; i += blockDim.x) sWa[i] = W1a[i];
    for (int i = threadIdx.x; i < 64 * 64; i += blockDim.x) sWb[i] = W1b[i];
    if (threadIdx.x < 64) { sba[threadIdx.x] = b1a[threadIdx.x]; sbb[threadIdx.x] = b1b[threadIdx.x]; }
    __syncthreads();

    int warp = (blockIdx.x * blockDim.x + threadIdx.x) >> 5;
    int nw   = (gridDim.x * blockDim.x) >> 5;
    int lane = threadIdx.x & 31;
    int j    = lane * 2;

    for (int node = warp; node < N_NODES; node += nw) {
        float z[7];
#pragma unroll
        for (int k = 0; k < 7; k++)
            z[k] = __ldg(&x[node * 7 + k]) + g_aggr1[node * 8 + k];

        float t0 = sba[j], t1 = sba[j + 1];
#pragma unroll
        for (int k = 0; k < 7; k++) {
            t0 += z[k] * sWa[k * 64 + j];
            t1 += z[k] * sWa[k * 64 + j + 1];
        }
        t0 = fmaxf(t0, 0.f);
        t1 = fmaxf(t1, 0.f);

        float a0 = sbb[j], a1 = sbb[j + 1];
#pragma unroll
        for (int k = 0; k < 64; k++) {
            float tk = __shfl_sync(0xffffffffu, (k & 1) ? t1 : t0, k >> 1);
            a0 += tk * sWb[k * 64 + j];
            a1 += tk * sWb[k * 64 + j + 1];
        }
        // outer relu from reference
        float2 o = make_float2(fmaxf(a0, 0.f), fmaxf(a1, 0.f));
        *reinterpret_cast<float2*>(g_h1 + node * 64 + j) = o;
    }
}

// ---------------- layer 2 edge pass (d = 64), half-warp per edge -----------
// weights in REGISTERS (no LDS in the hot loop); persistent grid-stride.
__global__ void edge2_kernel(const float* __restrict__ ea,
                             const int*   __restrict__ ei,
                             const float* __restrict__ We2,
                             const float* __restrict__ be2) {
    int tid = blockIdx.x * blockDim.x + threadIdx.x;
    int l   = threadIdx.x & 15;          // lane in half-warp -> output slice
    int hw  = tid >> 4;                  // global half-warp id
    int nhw = (gridDim.x * blockDim.x) >> 4;

    // per-lane weights: columns j..j+3 of We2 (4 input rows) + bias
    float w0x, w0y, w0z, w0w, w1x, w1y, w1z, w1w;
    float w2x, w2y, w2z, w2w, w3x, w3y, w3z, w3w;
    float4 bb;
    {
        float4 t0 = __ldg(reinterpret_cast<const float4*>(We2 + 0 * 64) + l);
        float4 t1 = __ldg(reinterpret_cast<const float4*>(We2 + 1 * 64) + l);
        float4 t2 = __ldg(reinterpret_cast<const float4*>(We2 + 2 * 64) + l);
        float4 t3 = __ldg(reinterpret_cast<const float4*>(We2 + 3 * 64) + l);
        w0x=t0.x; w0y=t0.y; w0z=t0.z; w0w=t0.w;
        w1x=t1.x; w1y=t1.y; w1z=t1.z; w1w=t1.w;
        w2x=t2.x; w2y=t2.y; w2z=t2.z; w2w=t2.w;
        w3x=t3.x; w3y=t3.y; w3z=t3.z; w3w=t3.w;
        bb = __ldg(reinterpret_cast<const float4*>(be2) + l);
    }

    for (int e = hw; e < N_EDGES; e += nhw) {
        int src = __ldg(&ei[e]);
        int dst = __ldg(&ei[N_EDGES + e]);
        float4 a = __ldg(reinterpret_cast<const float4*>(ea) + e);

        float m0 = bb.x + a.x*w0x + a.y*w1x + a.z*w2x + a.w*w3x;
        float m1 = bb.y + a.x*w0y + a.y*w1y + a.z*w2y + a.w*w3y;
        float m2 = bb.z + a.x*w0z + a.y*w1z + a.z*w2z + a.w*w3z;
        float m3 = bb.w + a.x*w0w + a.y*w1w + a.z*w2w + a.w*w3w;

        float4 h = __ldg(reinterpret_cast<const float4*>(g_h1 + src * 64) + l);
        m0 = fmaxf(m0 + h.x, 0.f);
        m1 = fmaxf(m1 + h.y, 0.f);
        m2 = fmaxf(m2 + h.z, 0.f);
        m3 = fmaxf(m3 + h.w, 0.f);

        float* p = g_aggr2 + dst * 64 + l * 4;
        asm volatile("red.global.add.v4.f32 [%0], {%1, %2, %3, %4};"
                     :: "l"(p), "f"(m0), "f"(m1), "f"(m2), "f"(m3) : "memory");
    }
}

// ---------------- layer 2 node MLP (64->64->64) + pool, persistent ---------
__global__ void node2pool_kernel(const int*   __restrict__ batch,
                                 const float* __restrict__ W2a,
                                 const float* __restrict__ b2a,
                                 const float* __restrict__ W2b,
                                 const float* __restrict__ b2b) {
    __shared__ float sWa[64 * 64];
    __shared__ float sWb[64 * 64];
    __shared__ float sba[64];
    __shared__ float sbb[64];
    for (int i = threadIdx.x; i < 64 * 64; i += blockDim.x) { sWa[i] = W2a[i]; sWb[i] = W2b[i]; }
    if (threadIdx.x < 64) { sba[threadIdx.x] = b2a[threadIdx.x]; sbb[threadIdx.x] = b2b[threadIdx.x]; }
    __syncthreads();

    int warp = (blockIdx.x * blockDim.x + threadIdx.x) >> 5;
    int nw   = (gridDim.x * blockDim.x) >> 5;
    int lane = threadIdx.x & 31;
    int j    = lane * 2;

    for (int node = warp; node < N_NODES; node += nw) {
        float2 hv = *reinterpret_cast<const float2*>(g_h1 + node * 64 + j);
        float2 av = *reinterpret_cast<const float2*>(g_aggr2 + node * 64 + j);
        float z0 = hv.x + av.x;
        float z1 = hv.y + av.y;

        float t0 = sba[j], t1 = sba[j + 1];
#pragma unroll
        for (int k = 0; k < 64; k++) {
            float zk = __shfl_sync(0xffffffffu, (k & 1) ? z1 : z0, k >> 1);
            t0 += zk * sWa[k * 64 + j];
            t1 += zk * sWa[k * 64 + j + 1];
        }
        t0 = fmaxf(t0, 0.f);
        t1 = fmaxf(t1, 0.f);

        float a0 = sbb[j], a1 = sbb[j + 1];
#pragma unroll
        for (int k = 0; k < 64; k++) {
            float tk = __shfl_sync(0xffffffffu, (k & 1) ? t1 : t0, k >> 1);
            a0 += tk * sWb[k * 64 + j];
            a1 += tk * sWb[k * 64 + j + 1];
        }
        a0 = fmaxf(a0, 0.f);   // outer relu from reference
        a1 = fmaxf(a1, 0.f);

        int g = batch[node];
        float* p = g_sums + g * 64 + j;
        asm volatile("red.global.add.v2.f32 [%0], {%1, %2};"
                     :: "l"(p), "f"(a0), "f"(a1) : "memory");
        if (lane == 0) atomicAdd(&g_cnt[g], 1.0f);
    }
}

// ---------------- final FC: pooled[G,64] @ Wfc[64,12] + bfc -----------------
__global__ void fc_kernel(const float* __restrict__ Wfc,
                          const float* __restrict__ bfc,
                          float* __restrict__ out) {
    int i = blockIdx.x * blockDim.x + threadIdx.x;
    if (i >= N_GRAPHS * 12) return;
    int g = i / 12;
    int c = i % 12;
    float inv = 1.0f / fmaxf(g_cnt[g], 1.0f);
    float acc = 0.f;
#pragma unroll
    for (int k = 0; k < 64; k++)
        acc += g_sums[g * 64 + k] * Wfc[k * 12 + c];
    out[i] = bfc[c] + inv * acc;
}

// ---------------- launch ----------------------------------------------------
extern "C" void kernel_launch(void* const* d_in, const int* in_sizes, int n_in,
                              void* d_out, int out_size) {
    const float* x    = (const float*)d_in[0];
    const float* ea   = (const float*)d_in[1];
    const int*   ei   = (const int*)  d_in[2];
    const int*   batch= (const int*)  d_in[3];
    const float* We1  = (const float*)d_in[4];
    const float* be1  = (const float*)d_in[5];
    const float* W1a  = (const float*)d_in[6];
    const float* b1a  = (const float*)d_in[7];
    const float* W1b  = (const float*)d_in[8];
    const float* b1b  = (const float*)d_in[9];
    const float* We2  = (const float*)d_in[10];
    const float* be2  = (const float*)d_in[11];
    const float* W2a  = (const float*)d_in[12];
    const float* b2a  = (const float*)d_in[13];
    const float* W2b  = (const float*)d_in[14];
    const float* b2b  = (const float*)d_in[15];
    const float* Wfc  = (const float*)d_in[16];
    const float* bfc  = (const float*)d_in[17];
    float* out = (float*)d_out;

    zero_kernel<<<(ZERO_TOTAL4 + 255) / 256, 256>>>();
    edge1_kernel<<<592, 256>>>(x, ea, ei, We1, be1);
    node1_kernel<<<592, 256>>>(x, W1a, b1a, W1b, b1b);
    edge2_kernel<<<1184, 256>>>(ea, ei, We2, be2);
    node2pool_kernel<<<592, 256>>>(batch, W2a, b2a, W2b, b2b);
    fc_kernel<<<(N_GRAPHS * 12 + 255) / 256, 256>>>(Wfc, bfc, out);
}